// round 14
// baseline (speedup 1.0000x reference)
#include <cuda_runtime.h>
#include <cstddef>

// PCEN: out = (x / (FLOOR + ema(x))^alpha + delta)^(1/root) - delta^(1/root)
// ema: m_t = s*x_t + (1-s)*m_{t-1}, m_0 = x_0, s = 0.025.
//
// R14: the untested cell of the config space: LDG.64 lanes (float2 — the
// highest-rate family measured, R6 5.75 TB/s) at NC=8 (compulsory-only DRAM
// traffic) with U=16 tiles (known register footprint ~125, no spill) and the
// static double-buffered pipeline. 1024 warps in 1024 single-warp blocks
// (~6.9 blocks/SM, even spread). HALO=256, stcs stores, launch_bounds(32,1).

namespace {
constexpr int   Bn = 64, Tn = 4096, Cn = 128;
constexpr float S_COEF = 0.025f;
constexpr float INV_S  = 40.0f;           // 1/s
constexpr float OMS    = 0.975f;
constexpr float FLOORV = 1e-6f;
constexpr int   NC     = 8;               // chunks along T
constexpr int   CHUNK  = Tn / NC;         // 512
constexpr int   HALO   = 256;             // burn-in rows (decay ~1.5e-3)
constexpr int   U      = 16;              // rows per tile
constexpr int   THREADS = 32;             // 1 warp/block
constexpr int   NWARPS  = Bn * NC * 2;    // 1024 float2-warps
constexpr int   NBLOCKS = NWARPS;         // 1024 blocks
constexpr int   STRIDE  = Cn / 2;         // float2 elems per T-row
static_assert(CHUNK % U == 0 && HALO % U == 0, "tiles must divide regions");
static_assert((CHUNK / U) % 2 == 0 && ((CHUNK + HALO) / U) % 2 == 0,
              "double-buffer loop needs even tile count");
}

__device__ __forceinline__ float f_lg2(float x) {
    float r; asm("lg2.approx.f32 %0, %1;" : "=f"(r) : "f"(x)); return r;
}
__device__ __forceinline__ float f_ex2(float x) {
    float r; asm("ex2.approx.f32 %0, %1;" : "=f"(r) : "f"(x)); return r;
}
__device__ __forceinline__ float f_sqt(float x) {
    float r; asm("sqrt.approx.f32 %0, %1;" : "=f"(r) : "f"(x)); return r;
}

// Pointwise PCEN. mp = m/S (scaled EMA state). SQ = (1/root == 0.5) fast path.
template <bool SQ>
__device__ __forceinline__ float pcen_pt(float xv, float mp, float na, float d,
                                         float ri, float t3) {
    float mm     = fmaf(S_COEF, mp, FLOORV);       // FLOOR + m (off the chain)
    float inv_t1 = f_ex2(na * f_lg2(mm));          // (FLOOR+m)^(-alpha)
    float y      = fmaf(xv, inv_t1, d);            // x/term1 + delta
    float t2     = SQ ? f_sqt(y) : f_ex2(ri * f_lg2(y));
    return t2 - t3;
}

// Consume one U-row float2 tile held in registers. emit is warp-uniform.
template <bool SQ>
__device__ __forceinline__ void consume_tile(const float2* __restrict__ xs,
                                             bool emit, float2* __restrict__ po,
                                             int emit_off, float& mx, float& my,
                                             float2 na, float2 d, float2 ri,
                                             float2 t3) {
    if (emit) {
        float2* pot = po + (size_t)emit_off * STRIDE;
        #pragma unroll
        for (int i = 0; i < U; ++i) {
            mx = fmaf(OMS, mx, xs[i].x);           // 2 independent chains
            my = fmaf(OMS, my, xs[i].y);
            float2 o;
            o.x = pcen_pt<SQ>(xs[i].x, mx, na.x, d.x, ri.x, t3.x);
            o.y = pcen_pt<SQ>(xs[i].y, my, na.y, d.y, ri.y, t3.y);
            __stcs(pot + i * STRIDE, o);
        }
    } else {
        #pragma unroll
        for (int i = 0; i < U; ++i) {
            mx = fmaf(OMS, mx, xs[i].x);
            my = fmaf(OMS, my, xs[i].y);
        }
    }
}

template <bool SQ>
__device__ __forceinline__ void run_seq(const float2* __restrict__ p,
                                        float2* __restrict__ po,
                                        int NH, int NT,
                                        float2 na, float2 d, float2 ri, float2 t3) {
    // scaled EMA state m' = m/S. Init m' = 40*x0 so consuming row 0 of tile 0
    // yields m = x[tstart] (exact for chunk 0 through the normal emit path).
    float2 x0 = p[0];
    float mx = INV_S * x0.x;
    float my = INV_S * x0.y;

    float2 bufA[U], bufB[U];
    #pragma unroll
    for (int i = 0; i < U; ++i) bufA[i] = p[i * STRIDE];    // preload tile 0

    // NT is even (32 or 48): tile t+1 always exists inside the loop.
    for (int t = 0; t < NT; t += 2) {
        const float2* p1 = p + (size_t)(t + 1) * U * STRIDE;
        #pragma unroll
        for (int i = 0; i < U; ++i) bufB[i] = p1[i * STRIDE];   // prefetch t+1

        consume_tile<SQ>(bufA, t >= NH, po, (t - NH) * U, mx, my, na, d, ri, t3);

        if (t + 2 < NT) {
            const float2* p2 = p + (size_t)(t + 2) * U * STRIDE;
            #pragma unroll
            for (int i = 0; i < U; ++i) bufA[i] = p2[i * STRIDE];  // prefetch t+2
        }

        consume_tile<SQ>(bufB, t + 1 >= NH, po, (t + 1 - NH) * U, mx, my, na, d, ri, t3);
    }
}

__global__ void __launch_bounds__(THREADS, 1)
pcen_kernel(const float* __restrict__ x,
            const float* __restrict__ alpha,
            const float* __restrict__ delta,
            const float* __restrict__ root,
            float* __restrict__ out) {
    int w    = blockIdx.x;                // one warp per block
    int lane = threadIdx.x;               // 0..31

    // warp -> (b, chunk, half); thread -> 2 channels
    int b     = w >> 4;
    int r     = w & 15;
    int chunk = r >> 1;
    int half  = r & 1;
    int c     = half * 64 + lane * 2;

    // per-channel constants (x2)
    float2 a2 = *(const float2*)(alpha + c);
    float2 d2 = *(const float2*)(delta + c);
    float2 r2 = *(const float2*)(root  + c);

    float2 na, ri, t3;
    na.x = -fminf(a2.x, 1.0f);
    na.y = -fminf(a2.y, 1.0f);
    ri.x = 1.0f / fmaxf(r2.x, 1.0f);
    ri.y = 1.0f / fmaxf(r2.y, 1.0f);
    bool sq = (ri.x == 0.5f) && (ri.y == 0.5f);
    // term3 via the SAME approx path as term2 so the x->0 limit cancels exactly
    t3.x = sq ? f_sqt(d2.x) : f_ex2(ri.x * f_lg2(d2.x));
    t3.y = sq ? f_sqt(d2.y) : f_ex2(ri.y * f_lg2(d2.y));

    int t0     = chunk * CHUNK;
    int tstart = (chunk == 0) ? 0 : (t0 - HALO);
    int NH     = (t0 - tstart) / U;          // 0 (chunk 0) or 16
    int NT     = NH + CHUNK / U;             // 32 or 48 (always even)

    const float2* px = (const float2*)(x   + ((size_t)b * Tn + tstart) * Cn + c);
    float2*       po = (float2*)      (out + ((size_t)b * Tn + t0)     * Cn + c);

    if (sq) run_seq<true >(px, po, NH, NT, na, d2, ri, t3);
    else    run_seq<false>(px, po, NH, NT, na, d2, ri, t3);
}

extern "C" void kernel_launch(void* const* d_in, const int* in_sizes, int n_in,
                              void* d_out, int out_size) {
    const float* x     = (const float*)d_in[0];
    const float* alpha = (const float*)d_in[1];
    const float* delta = (const float*)d_in[2];
    const float* root  = (const float*)d_in[3];
    float*       out   = (float*)d_out;
    (void)in_sizes; (void)n_in; (void)out_size;

    pcen_kernel<<<NBLOCKS, THREADS>>>(x, alpha, delta, root, out);
}

// round 15
// speedup vs baseline: 1.0277x; 1.0277x over previous
#include <cuda_runtime.h>
#include <cstdint>
#include <cstddef>

// PCEN: out = (x / (FLOOR + ema(x))^alpha + delta)^(1/root) - delta^(1/root)
// ema: m_t = s*x_t + (1-s)*m_{t-1}, m_0 = x_0, s = 0.025.
//
// R15: bulk-async read engine. One 128-thread block per (b,chunk). Thread 0
// streams the block's contiguous x region through a 4-stage smem ring with
// cp.async.bulk.shared::cta.global (8 KB per tile, mbarrier expect_tx paced).
// Consumers read their channel column from smem (conflict-free), run the EMA
// + PCEN math, and store straight to gmem with .cs (write path unchanged).
// Reads become large sequential transfers with ~12 MB chip-wide in flight,
// decoupled from register pressure. NC=8, CHUNK=512, HALO=256.

namespace {
constexpr int   Bn = 64, Tn = 4096, Cn = 128;
constexpr float S_COEF = 0.025f;
constexpr float INV_S  = 40.0f;           // 1/s
constexpr float OMS    = 0.975f;
constexpr float FLOORV = 1e-6f;
constexpr int   NC     = 8;               // chunks along T
constexpr int   CHUNK  = Tn / NC;         // 512
constexpr int   HALO   = 256;             // burn-in rows (decay ~1.5e-3)
constexpr int   U      = 16;              // rows per stage (8 KB)
constexpr int   NSTAGE = 4;               // smem ring depth
constexpr int   THREADS = 128;            // 1 thread = 1 channel
constexpr int   NBLOCKS = Bn * NC;        // 512 blocks
constexpr int   STAGE_BYTES = U * Cn * 4; // 8192
static_assert(CHUNK % U == 0 && HALO % U == 0, "tiles must divide regions");
}

__device__ __forceinline__ uint32_t smem_u32(const void* p) {
    uint32_t a;
    asm("{ .reg .u64 t; cvta.to.shared.u64 t, %1; cvt.u32.u64 %0, t; }"
        : "=r"(a) : "l"(p));
    return a;
}

__device__ __forceinline__ void mbar_init(uint32_t mb, uint32_t cnt) {
    asm volatile("mbarrier.init.shared.b64 [%0], %1;" :: "r"(mb), "r"(cnt) : "memory");
}
__device__ __forceinline__ void mbar_inval(uint32_t mb) {
    asm volatile("mbarrier.inval.shared.b64 [%0];" :: "r"(mb) : "memory");
}

// expect_tx + 1D bulk load global->shared completing on the mbarrier
__device__ __forceinline__ void bulk_load(uint32_t dst, const float* src, uint32_t mb) {
    asm volatile("mbarrier.arrive.expect_tx.shared.b64 _, [%0], %1;"
                 :: "r"(mb), "r"((uint32_t)STAGE_BYTES) : "memory");
    asm volatile("cp.async.bulk.shared::cta.global.mbarrier::complete_tx::bytes "
                 "[%0], [%1], %2, [%3];"
                 :: "r"(dst), "l"((const void*)src), "r"((uint32_t)STAGE_BYTES), "r"(mb)
                 : "memory");
}

__device__ __forceinline__ void mbar_wait(uint32_t mb, uint32_t parity) {
    uint32_t done;
    asm volatile(
        "{\n\t.reg .pred p;\n\t"
        "mbarrier.try_wait.parity.acquire.cta.shared::cta.b64 p, [%1], %2;\n\t"
        "selp.b32 %0, 1, 0, p;\n\t}"
        : "=r"(done) : "r"(mb), "r"(parity) : "memory");
    if (!done) {
        asm volatile(
            "{\n\t.reg .pred P1;\n\t"
            "WL_%=:\n\t"
            "mbarrier.try_wait.parity.acquire.cta.shared::cta.b64 P1, [%0], %1, 0x989680;\n\t"
            "@P1 bra.uni WD_%=;\n\t"
            "bra.uni WL_%=;\n\t"
            "WD_%=:\n\t}"
            :: "r"(mb), "r"(parity) : "memory");
    }
}

__device__ __forceinline__ float f_lg2(float x) {
    float r; asm("lg2.approx.f32 %0, %1;" : "=f"(r) : "f"(x)); return r;
}
__device__ __forceinline__ float f_ex2(float x) {
    float r; asm("ex2.approx.f32 %0, %1;" : "=f"(r) : "f"(x)); return r;
}
__device__ __forceinline__ float f_sqt(float x) {
    float r; asm("sqrt.approx.f32 %0, %1;" : "=f"(r) : "f"(x)); return r;
}

// Pointwise PCEN. mp = m/S (scaled EMA state). SQ = (1/root == 0.5) fast path.
template <bool SQ>
__device__ __forceinline__ float pcen_pt(float xv, float mp, float na, float d,
                                         float ri, float t3) {
    float mm     = fmaf(S_COEF, mp, FLOORV);       // FLOOR + m (off the chain)
    float inv_t1 = f_ex2(na * f_lg2(mm));          // (FLOOR+m)^(-alpha)
    float y      = fmaf(xv, inv_t1, d);            // x/term1 + delta
    float t2     = SQ ? f_sqt(y) : f_ex2(ri * f_lg2(y));
    return t2 - t3;
}

template <bool SQ>
__device__ __forceinline__ void run_pipe(const float* __restrict__ gsrc,
                                         float* __restrict__ po,
                                         float (*stage)[U][Cn],
                                         uint32_t stage0, uint32_t mbar0,
                                         int NH, int NT, int c,
                                         float na, float d, float ri, float t3) {
    // prologue: fill the ring
    if (threadIdx.x == 0) {
        #pragma unroll
        for (int t = 0; t < NSTAGE; ++t)
            bulk_load(stage0 + t * STAGE_BYTES, gsrc + (size_t)t * U * Cn,
                      mbar0 + 8 * t);
    }

    float m = 0.0f;   // set from first row after stage 0 lands
    for (int t = 0; t < NT; ++t) {
        int s = t & (NSTAGE - 1);
        uint32_t mb = mbar0 + 8 * s;
        mbar_wait(mb, (t >> 2) & 1);

        const float* sp = &stage[s][0][c];
        if (t == 0) m = INV_S * sp[0];   // m' = m/S; row0 folds to m = x[tstart]

        if (t >= NH) {
            float* pot = po + (size_t)(t - NH) * U * Cn;
            float xs[U];
            #pragma unroll
            for (int i = 0; i < U; ++i) xs[i] = sp[i * Cn];   // batched LDS
            #pragma unroll
            for (int i = 0; i < U; ++i) {
                m = fmaf(OMS, m, xs[i]);                      // 4-cyc chain
                __stcs(pot + i * Cn, pcen_pt<SQ>(xs[i], m, na, d, ri, t3));
            }
        } else {
            float xs[U];
            #pragma unroll
            for (int i = 0; i < U; ++i) xs[i] = sp[i * Cn];
            #pragma unroll
            for (int i = 0; i < U; ++i) m = fmaf(OMS, m, xs[i]);
        }

        __syncthreads();                 // everyone done reading stage s
        if (threadIdx.x == 0 && t + NSTAGE < NT)
            bulk_load(stage0 + s * STAGE_BYTES,
                      gsrc + (size_t)(t + NSTAGE) * U * Cn, mb);
    }
}

__global__ void __launch_bounds__(THREADS, 1)
pcen_kernel(const float* __restrict__ x,
            const float* __restrict__ alpha,
            const float* __restrict__ delta,
            const float* __restrict__ root,
            float* __restrict__ out) {
    __shared__ __align__(1024) float stage[NSTAGE][U][Cn];       // 32 KB
    __shared__ __align__(8) unsigned long long mbar[NSTAGE];

    int b     = blockIdx.x >> 3;
    int chunk = blockIdx.x & 7;
    int c     = threadIdx.x;             // channel

    // per-channel constants
    float a  = fminf(alpha[c], 1.0f);
    float d  = delta[c];
    float ri = 1.0f / fmaxf(root[c], 1.0f);
    float na = -a;
    // block-uniform SQ decision (barriers live inside the pipeline)
    int sq = __syncthreads_and((ri == 0.5f) ? 1 : 0);
    // term3 via the SAME approx path as term2 so the x->0 limit cancels exactly
    float t3 = sq ? f_sqt(d) : f_ex2(ri * f_lg2(d));

    uint32_t stage0 = smem_u32(&stage[0][0][0]);
    uint32_t mbar0  = smem_u32(&mbar[0]);

    if (threadIdx.x == 0) {
        #pragma unroll
        for (int s = 0; s < NSTAGE; ++s) mbar_init(mbar0 + 8 * s, 1);
        asm volatile("fence.proxy.async.shared::cta;" ::: "memory");
    }
    __syncthreads();

    int t0     = chunk * CHUNK;
    int tstart = (chunk == 0) ? 0 : (t0 - HALO);
    int NH     = (t0 - tstart) / U;      // 0 (chunk 0) or 16
    int NT     = NH + CHUNK / U;         // 32 or 48

    const float* gsrc = x   + ((size_t)b * Tn + tstart) * Cn;
    float*       po   = out + ((size_t)b * Tn + t0)     * Cn + c;

    if (sq) run_pipe<true >(gsrc, po, stage, stage0, mbar0, NH, NT, c, na, d, ri, t3);
    else    run_pipe<false>(gsrc, po, stage, stage0, mbar0, NH, NT, c, na, d, ri, t3);

    __syncthreads();
    if (threadIdx.x == 0) {
        #pragma unroll
        for (int s = 0; s < NSTAGE; ++s) mbar_inval(mbar0 + 8 * s);
    }
}

extern "C" void kernel_launch(void* const* d_in, const int* in_sizes, int n_in,
                              void* d_out, int out_size) {
    const float* x     = (const float*)d_in[0];
    const float* alpha = (const float*)d_in[1];
    const float* delta = (const float*)d_in[2];
    const float* root  = (const float*)d_in[3];
    float*       out   = (float*)d_out;
    (void)in_sizes; (void)n_in; (void)out_size;

    pcen_kernel<<<NBLOCKS, THREADS>>>(x, alpha, delta, root, out);
}

// round 17
// speedup vs baseline: 1.0282x; 1.0006x over previous
#include <cuda_runtime.h>
#include <cstdint>
#include <cstddef>

// PCEN: out = (x / (FLOOR + ema(x))^alpha + delta)^(1/root) - delta^(1/root)
// ema: m_t = s*x_t + (1-s)*m_{t-1}, m_0 = x_0, s = 0.025.
//
// R17: R16 (symmetric bulk-async: TMA-class 8 KB reads AND writes through
// smem rings) with the output-buffer reuse RACE FIXED: before STS into out
// buffer os at emit e, thread 0 drains bulk-store groups to <=1 outstanding
// (store e-2 finished reading) and a __syncthreads() publishes that to all
// threads. NC=8, CHUNK=512, HALO=256, 512 blocks x 128 threads.

namespace {
constexpr int   Bn = 64, Tn = 4096, Cn = 128;
constexpr float S_COEF = 0.025f;
constexpr float INV_S  = 40.0f;           // 1/s
constexpr float OMS    = 0.975f;
constexpr float FLOORV = 1e-6f;
constexpr int   NC     = 8;               // chunks along T
constexpr int   CHUNK  = Tn / NC;         // 512
constexpr int   HALO   = 256;             // burn-in rows (decay ~1.5e-3)
constexpr int   U      = 16;              // rows per stage (8 KB)
constexpr int   NSTAGE = 4;               // input smem ring depth
constexpr int   THREADS = 128;            // 1 thread = 1 channel
constexpr int   NBLOCKS = Bn * NC;        // 512 blocks
constexpr int   STAGE_BYTES = U * Cn * 4; // 8192
static_assert(CHUNK % U == 0 && HALO % U == 0, "tiles must divide regions");
}

__device__ __forceinline__ uint32_t smem_u32(const void* p) {
    uint32_t a;
    asm("{ .reg .u64 t; cvta.to.shared.u64 t, %1; cvt.u32.u64 %0, t; }"
        : "=r"(a) : "l"(p));
    return a;
}

__device__ __forceinline__ void mbar_init(uint32_t mb, uint32_t cnt) {
    asm volatile("mbarrier.init.shared.b64 [%0], %1;" :: "r"(mb), "r"(cnt) : "memory");
}
__device__ __forceinline__ void mbar_inval(uint32_t mb) {
    asm volatile("mbarrier.inval.shared.b64 [%0];" :: "r"(mb) : "memory");
}

// expect_tx + 1D bulk load global->shared completing on the mbarrier
__device__ __forceinline__ void bulk_load(uint32_t dst, const float* src, uint32_t mb) {
    asm volatile("mbarrier.arrive.expect_tx.shared.b64 _, [%0], %1;"
                 :: "r"(mb), "r"((uint32_t)STAGE_BYTES) : "memory");
    asm volatile("cp.async.bulk.shared::cta.global.mbarrier::complete_tx::bytes "
                 "[%0], [%1], %2, [%3];"
                 :: "r"(dst), "l"((const void*)src), "r"((uint32_t)STAGE_BYTES), "r"(mb)
                 : "memory");
}

// 1D bulk store shared->global (bulk-group tracked)
__device__ __forceinline__ void bulk_store(float* dst, uint32_t src) {
    asm volatile("cp.async.bulk.global.shared::cta.bulk_group [%0], [%1], %2;"
                 :: "l"((void*)dst), "r"(src), "r"((uint32_t)STAGE_BYTES)
                 : "memory");
    asm volatile("cp.async.bulk.commit_group;" ::: "memory");
}

__device__ __forceinline__ void mbar_wait(uint32_t mb, uint32_t parity) {
    uint32_t done;
    asm volatile(
        "{\n\t.reg .pred p;\n\t"
        "mbarrier.try_wait.parity.acquire.cta.shared::cta.b64 p, [%1], %2;\n\t"
        "selp.b32 %0, 1, 0, p;\n\t}"
        : "=r"(done) : "r"(mb), "r"(parity) : "memory");
    if (!done) {
        asm volatile(
            "{\n\t.reg .pred P1;\n\t"
            "WL_%=:\n\t"
            "mbarrier.try_wait.parity.acquire.cta.shared::cta.b64 P1, [%0], %1, 0x989680;\n\t"
            "@P1 bra.uni WD_%=;\n\t"
            "bra.uni WL_%=;\n\t"
            "WD_%=:\n\t}"
            :: "r"(mb), "r"(parity) : "memory");
    }
}

__device__ __forceinline__ float f_lg2(float x) {
    float r; asm("lg2.approx.f32 %0, %1;" : "=f"(r) : "f"(x)); return r;
}
__device__ __forceinline__ float f_ex2(float x) {
    float r; asm("ex2.approx.f32 %0, %1;" : "=f"(r) : "f"(x)); return r;
}
__device__ __forceinline__ float f_sqt(float x) {
    float r; asm("sqrt.approx.f32 %0, %1;" : "=f"(r) : "f"(x)); return r;
}

// Pointwise PCEN. mp = m/S (scaled EMA state). SQ = (1/root == 0.5) fast path.
template <bool SQ>
__device__ __forceinline__ float pcen_pt(float xv, float mp, float na, float d,
                                         float ri, float t3) {
    float mm     = fmaf(S_COEF, mp, FLOORV);       // FLOOR + m (off the chain)
    float inv_t1 = f_ex2(na * f_lg2(mm));          // (FLOOR+m)^(-alpha)
    float y      = fmaf(xv, inv_t1, d);            // x/term1 + delta
    float t2     = SQ ? f_sqt(y) : f_ex2(ri * f_lg2(y));
    return t2 - t3;
}

template <bool SQ>
__device__ __forceinline__ void run_pipe(const float* __restrict__ gsrc,
                                         float* __restrict__ gout,
                                         float (*stage)[U][Cn],
                                         float (*ostage)[U][Cn],
                                         uint32_t stage0, uint32_t ostage0,
                                         uint32_t mbar0,
                                         int NH, int NT, int c,
                                         float na, float d, float ri, float t3) {
    // prologue: fill the input ring
    if (threadIdx.x == 0) {
        #pragma unroll
        for (int t = 0; t < NSTAGE; ++t)
            bulk_load(stage0 + t * STAGE_BYTES, gsrc + (size_t)t * U * Cn,
                      mbar0 + 8 * t);
    }

    float m = 0.0f;   // set from first row after stage 0 lands
    for (int t = 0; t < NT; ++t) {
        int s = t & (NSTAGE - 1);
        uint32_t mb = mbar0 + 8 * s;
        mbar_wait(mb, (t >> 2) & 1);

        const float* sp = &stage[s][0][c];
        if (t == 0) m = INV_S * sp[0];   // m' = m/S; row0 folds to m = x[tstart]

        float xs[U];
        #pragma unroll
        for (int i = 0; i < U; ++i) xs[i] = sp[i * Cn];       // batched LDS

        if (t >= NH) {
            int e  = t - NH;
            int os = e & 1;
            // ---- reuse guard: store e-2 must have finished READING ostage[os]
            if (e >= 2) {
                if (threadIdx.x == 0)
                    asm volatile("cp.async.bulk.wait_group.read 1;" ::: "memory");
                __syncthreads();          // publish drain to ALL threads
            }
            float* op = &ostage[os][0][c];
            #pragma unroll
            for (int i = 0; i < U; ++i) {
                m = fmaf(OMS, m, xs[i]);                      // 4-cyc chain
                op[i * Cn] = pcen_pt<SQ>(xs[i], m, na, d, ri, t3);  // STS
            }
            __syncthreads();             // results visible + stage s consumed
            if (threadIdx.x == 0) {
                asm volatile("fence.proxy.async.shared::cta;" ::: "memory");
                bulk_store(gout + (size_t)e * U * Cn, ostage0 + os * STAGE_BYTES);
                if (t + NSTAGE < NT)
                    bulk_load(stage0 + s * STAGE_BYTES,
                              gsrc + (size_t)(t + NSTAGE) * U * Cn, mb);
            }
        } else {
            #pragma unroll
            for (int i = 0; i < U; ++i) m = fmaf(OMS, m, xs[i]);
            __syncthreads();             // stage s consumed
            if (threadIdx.x == 0 && t + NSTAGE < NT)
                bulk_load(stage0 + s * STAGE_BYTES,
                          gsrc + (size_t)(t + NSTAGE) * U * Cn, mb);
        }
    }
    // drain pending bulk stores before exit
    if (threadIdx.x == 0)
        asm volatile("cp.async.bulk.wait_group.read 0;" ::: "memory");
}

__global__ void __launch_bounds__(THREADS, 1)
pcen_kernel(const float* __restrict__ x,
            const float* __restrict__ alpha,
            const float* __restrict__ delta,
            const float* __restrict__ root,
            float* __restrict__ out) {
    __shared__ __align__(1024) float stage [NSTAGE][U][Cn];      // 32 KB in
    __shared__ __align__(1024) float ostage[2][U][Cn];           // 16 KB out
    __shared__ __align__(8) unsigned long long mbar[NSTAGE];

    int b     = blockIdx.x >> 3;
    int chunk = blockIdx.x & 7;
    int c     = threadIdx.x;             // channel

    // per-channel constants
    float a  = fminf(alpha[c], 1.0f);
    float d  = delta[c];
    float ri = 1.0f / fmaxf(root[c], 1.0f);
    float na = -a;
    // block-uniform SQ decision (barriers live inside the pipeline)
    int sq = __syncthreads_and((ri == 0.5f) ? 1 : 0);
    // term3 via the SAME approx path as term2 so the x->0 limit cancels exactly
    float t3 = sq ? f_sqt(d) : f_ex2(ri * f_lg2(d));

    uint32_t stage0  = smem_u32(&stage[0][0][0]);
    uint32_t ostage0 = smem_u32(&ostage[0][0][0]);
    uint32_t mbar0   = smem_u32(&mbar[0]);

    if (threadIdx.x == 0) {
        #pragma unroll
        for (int s = 0; s < NSTAGE; ++s) mbar_init(mbar0 + 8 * s, 1);
        asm volatile("fence.proxy.async.shared::cta;" ::: "memory");
    }
    __syncthreads();

    int t0     = chunk * CHUNK;
    int tstart = (chunk == 0) ? 0 : (t0 - HALO);
    int NH     = (t0 - tstart) / U;      // 0 (chunk 0) or 16
    int NT     = NH + CHUNK / U;         // 32 or 48

    const float* gsrc = x   + ((size_t)b * Tn + tstart) * Cn;
    float*       gout = out + ((size_t)b * Tn + t0)     * Cn;

    if (sq) run_pipe<true >(gsrc, gout, stage, ostage, stage0, ostage0, mbar0,
                            NH, NT, c, na, d, ri, t3);
    else    run_pipe<false>(gsrc, gout, stage, ostage, stage0, ostage0, mbar0,
                            NH, NT, c, na, d, ri, t3);

    __syncthreads();
    if (threadIdx.x == 0) {
        #pragma unroll
        for (int s = 0; s < NSTAGE; ++s) mbar_inval(mbar0 + 8 * s);
    }
}

extern "C" void kernel_launch(void* const* d_in, const int* in_sizes, int n_in,
                              void* d_out, int out_size) {
    const float* x     = (const float*)d_in[0];
    const float* alpha = (const float*)d_in[1];
    const float* delta = (const float*)d_in[2];
    const float* root  = (const float*)d_in[3];
    float*       out   = (float*)d_out;
    (void)in_sizes; (void)n_in; (void)out_size;

    pcen_kernel<<<NBLOCKS, THREADS>>>(x, alpha, delta, root, out);
}